// round 2
// baseline (speedup 1.0000x reference)
#include <cuda_runtime.h>
#include <cstdint>

// ======================= problem constants =======================
constexpr int MB = 8192;   // batch (GEMM M)
constexpr int NB = 2048;   // out features (GEMM N)
constexpr int KB = 2048;   // in features (GEMM K)

constexpr int BM = 128;
constexpr int BN = 128;
constexpr int BK = 64;
constexpr int KITERS = KB / BK;   // 32
constexpr int NS = 4;             // cp.async pipeline stages

// smem: pitch-80 rows (64 data bytes + 16 pad) -> conflict-free 4B fragment loads
constexpr int PITCH = 80;
constexpr int STAGE_A = BM * PITCH;            // 10240
constexpr int STAGE_B = BN * PITCH;            // 10240
constexpr int SMEM_A_OFF = 0;
constexpr int SMEM_B_OFF = NS * STAGE_A;       // 40960
constexpr int SMEM_TOTAL = NS * (STAGE_A + STAGE_B);  // 81920

// int8 sign scratch
__device__ __align__(16) signed char g_xs[(size_t)MB * KB];  // 16 MB
__device__ __align__(16) signed char g_ws[(size_t)NB * KB];  //  4 MB

// ======================= helpers =======================
__device__ __forceinline__ uint32_t smem_u32(const void* p) {
    uint32_t a;
    asm("{ .reg .u64 t; cvta.to.shared.u64 t, %1; cvt.u32.u64 %0, t; }" : "=r"(a) : "l"(p));
    return a;
}

__device__ __forceinline__ void cp16(uint32_t dst, const void* src) {
    asm volatile("cp.async.cg.shared.global [%0], [%1], 16;" :: "r"(dst), "l"(src));
}
__device__ __forceinline__ void cp_commit() {
    asm volatile("cp.async.commit_group;" ::: "memory");
}
template <int N>
__device__ __forceinline__ void cp_wait() {
    asm volatile("cp.async.wait_group %0;" :: "n"(N) : "memory");
}

__device__ __forceinline__ uint32_t lds32(uint32_t addr) {
    uint32_t v;
    asm volatile("ld.shared.b32 %0, [%1];" : "=r"(v) : "r"(addr));
    return v;
}

// s8 x s8 -> s32, m16n8k32, A row-major, B col-major
__device__ __forceinline__ void imma16832(
    int32_t* d, const uint32_t* a, const uint32_t* b)
{
    asm volatile(
        "mma.sync.aligned.m16n8k32.row.col.s32.s8.s8.s32 "
        "{%0,%1,%2,%3}, {%4,%5,%6,%7}, {%8,%9}, {%0,%1,%2,%3};"
        : "+r"(d[0]), "+r"(d[1]), "+r"(d[2]), "+r"(d[3])
        : "r"(a[0]), "r"(a[1]), "r"(a[2]), "r"(a[3]),
          "r"(b[0]), "r"(b[1]));
}

// ======================= quantize: fp32 -> s8 sign =======================
// +1 -> 0x01, -1 -> 0xFF, 0 -> 0x00
__global__ void __launch_bounds__(256)
quant_sign_kernel(const float* __restrict__ in, signed char* __restrict__ out, int n16)
{
    int i = blockIdx.x * 256 + threadIdx.x;
    if (i >= n16) return;
    const float4* p = reinterpret_cast<const float4*>(in) + (size_t)i * 4;
    uint32_t w[4];
#pragma unroll
    for (int j = 0; j < 4; j++) {
        float4 v = p[j];
        uint32_t b0 = v.x > 0.f ? 0x01u : (v.x < 0.f ? 0xFFu : 0x00u);
        uint32_t b1 = v.y > 0.f ? 0x01u : (v.y < 0.f ? 0xFFu : 0x00u);
        uint32_t b2 = v.z > 0.f ? 0x01u : (v.z < 0.f ? 0xFFu : 0x00u);
        uint32_t b3 = v.w > 0.f ? 0x01u : (v.w < 0.f ? 0xFFu : 0x00u);
        w[j] = b0 | (b1 << 8) | (b2 << 16) | (b3 << 24);
    }
    reinterpret_cast<uint4*>(out)[i] = make_uint4(w[0], w[1], w[2], w[3]);
}

// ======================= GEMM kernel =======================
// out[m,n] = sum_k xs[m,k]*ws[n,k] + bias[n]
// 8 warps: warp grid 4 (M) x 2 (N); warp tile 32 x 64.
__global__ void __launch_bounds__(256, 2)
tgemm_kernel(const signed char* __restrict__ xs, const signed char* __restrict__ ws,
             const float* __restrict__ bias, float* __restrict__ out)
{
    extern __shared__ unsigned char smem[];
    const uint32_t sb = smem_u32(smem);
    const uint32_t sA = sb + SMEM_A_OFF;
    const uint32_t sB = sb + SMEM_B_OFF;

    const int tid = threadIdx.x;
    const int wid = tid >> 5;
    const int lane = tid & 31;
    const int qr = lane >> 2;    // 0..7
    const int qc = lane & 3;     // 0..3

    const int tile_m = blockIdx.y;   // 0..63
    const int tile_n = blockIdx.x;   // 0..15

    const int warp_m = wid >> 1;     // 0..3 -> 32-row slab
    const int warp_n = wid & 1;      // 0..1 -> 64-col slab
    const int m_off = warp_m * 32;
    const int n_off = warp_n * 64;

    const signed char* ag0 = xs + (size_t)tile_m * BM * KB;
    const signed char* bg0 = ws + (size_t)tile_n * BN * KB;

    // per-thread load coords: 512 16B chunks per matrix per stage, 2 per thread
    // idx -> row = idx>>2, chunk col = idx&3
    auto load_stage = [&](int kk, int s) {
        const uint32_t a_s = sA + s * STAGE_A;
        const uint32_t b_s = sB + s * STAGE_B;
        const signed char* ag = ag0 + kk * BK;
        const signed char* bg = bg0 + kk * BK;
#pragma unroll
        for (int i = 0; i < 2; i++) {
            int idx = tid + i * 256;
            int r = idx >> 2, c = idx & 3;
            cp16(a_s + r * PITCH + c * 16, ag + (size_t)r * KB + c * 16);
        }
#pragma unroll
        for (int i = 0; i < 2; i++) {
            int idx = tid + i * 256;
            int r = idx >> 2, c = idx & 3;
            cp16(b_s + r * PITCH + c * 16, bg + (size_t)r * KB + c * 16);
        }
        cp_commit();
    };

    // accumulators: 2 m-tiles x 8 n-tiles x 4 regs
    int32_t acc[2][8][4];
#pragma unroll
    for (int mt = 0; mt < 2; mt++)
#pragma unroll
        for (int nt = 0; nt < 8; nt++)
#pragma unroll
            for (int r = 0; r < 4; r++) acc[mt][nt][r] = 0;

    // prologue: stages 0..NS-2
    load_stage(0, 0);
    load_stage(1, 1);
    load_stage(2, 2);

    // fragment base offsets (within a stage)
    const uint32_t a_base = (m_off + qr) * PITCH + qc * 4;
    const uint32_t b_base = (n_off + qr) * PITCH + qc * 4;

    for (int t = 0; t < KITERS; ++t) {
        const int s = t & (NS - 1);
        cp_wait<NS - 2>();
        __syncthreads();

        // issue next stage load (overwrites slot consumed last iter; safe post-sync)
        if (t + NS - 1 < KITERS) load_stage(t + NS - 1, (t + NS - 1) & (NS - 1));
        else cp_commit();   // keep group numbering aligned with wait_group N

        const uint32_t a_s = sA + s * STAGE_A + a_base;
        const uint32_t b_s = sB + s * STAGE_B + b_base;

#pragma unroll
        for (int ks = 0; ks < 2; ks++) {     // two k32 steps per BK=64
            const uint32_t ka = a_s + ks * 32;
            const uint32_t kb = b_s + ks * 32;
            uint32_t afr[2][4];
#pragma unroll
            for (int mt = 0; mt < 2; mt++) {
                const uint32_t base = ka + mt * 16 * PITCH;
                afr[mt][0] = lds32(base);
                afr[mt][1] = lds32(base + 8 * PITCH);
                afr[mt][2] = lds32(base + 16);
                afr[mt][3] = lds32(base + 8 * PITCH + 16);
            }
#pragma unroll
            for (int nt = 0; nt < 8; nt++) {
                const uint32_t base = kb + nt * 8 * PITCH;
                uint32_t bfr[2];
                bfr[0] = lds32(base);
                bfr[1] = lds32(base + 16);
                imma16832(acc[0][nt], afr[0], bfr);
                imma16832(acc[1][nt], afr[1], bfr);
            }
        }
    }

    // ======================= epilogue =======================
    const int gm0 = tile_m * BM + m_off + qr;
    const int gn0 = tile_n * BN + n_off + qc * 2;
#pragma unroll
    for (int mt = 0; mt < 2; mt++) {
#pragma unroll
        for (int nt = 0; nt < 8; nt++) {
            const int col = gn0 + nt * 8;
            const float2 bb = *reinterpret_cast<const float2*>(bias + col);
            const int row0 = gm0 + mt * 16;
            float2 v0, v1;
            v0.x = (float)acc[mt][nt][0] + bb.x;
            v0.y = (float)acc[mt][nt][1] + bb.y;
            v1.x = (float)acc[mt][nt][2] + bb.x;
            v1.y = (float)acc[mt][nt][3] + bb.y;
            *reinterpret_cast<float2*>(out + (size_t)row0 * NB + col) = v0;
            *reinterpret_cast<float2*>(out + (size_t)(row0 + 8) * NB + col) = v1;
        }
    }
}

// ======================= launch =======================
extern "C" void kernel_launch(void* const* d_in, const int* in_sizes, int n_in,
                              void* d_out, int out_size)
{
    const float* x    = (const float*)d_in[0];  // [8192, 2048]
    const float* w    = (const float*)d_in[1];  // [2048, 2048]
    const float* bias = (const float*)d_in[2];  // [2048]
    float* out = (float*)d_out;

    void* xs = nullptr; cudaGetSymbolAddress(&xs, g_xs);
    void* ws = nullptr; cudaGetSymbolAddress(&ws, g_ws);

    const int nx16 = MB * KB / 16;
    const int nw16 = NB * KB / 16;
    quant_sign_kernel<<<(nx16 + 255) / 256, 256>>>(x, (signed char*)xs, nx16);
    quant_sign_kernel<<<(nw16 + 255) / 256, 256>>>(w, (signed char*)ws, nw16);

    cudaFuncSetAttribute(tgemm_kernel, cudaFuncAttributeMaxDynamicSharedMemorySize, SMEM_TOTAL);
    tgemm_kernel<<<dim3(NB / BN, MB / BM), 256, SMEM_TOTAL>>>(
        (const signed char*)xs, (const signed char*)ws, bias, out);
}

// round 3
// speedup vs baseline: 1.0625x; 1.0625x over previous
#include <cuda_runtime.h>
#include <cstdint>

// ======================= problem constants =======================
constexpr int MB = 8192;   // batch (GEMM M)
constexpr int NB = 2048;   // out features (GEMM N)
constexpr int KB = 2048;   // in features (GEMM K)

constexpr int BM = 128;
constexpr int BN = 128;
constexpr int BK = 128;            // 128 s8 = one SW128 row
constexpr int KITERS = KB / BK;    // 16
constexpr int NS = 3;              // cp.async pipeline stages

constexpr int STAGE = BM * BK;     // 16384 bytes per matrix per stage
constexpr int SMEM_A_OFF = 0;
constexpr int SMEM_B_OFF = NS * STAGE;            // 49152
constexpr int SMEM_TOTAL = 2 * NS * STAGE;        // 98304

// int8 sign scratch
__device__ __align__(16) signed char g_xs[(size_t)MB * KB];  // 16 MB
__device__ __align__(16) signed char g_ws[(size_t)NB * KB];  //  4 MB

// ======================= helpers =======================
__device__ __forceinline__ uint32_t smem_u32(const void* p) {
    uint32_t a;
    asm("{ .reg .u64 t; cvta.to.shared.u64 t, %1; cvt.u32.u64 %0, t; }" : "=r"(a) : "l"(p));
    return a;
}
__device__ __forceinline__ void cp16(uint32_t dst, const void* src) {
    asm volatile("cp.async.cg.shared.global [%0], [%1], 16;" :: "r"(dst), "l"(src));
}
__device__ __forceinline__ void cp_commit() {
    asm volatile("cp.async.commit_group;" ::: "memory");
}
template <int N>
__device__ __forceinline__ void cp_wait() {
    asm volatile("cp.async.wait_group %0;" :: "n"(N) : "memory");
}
__device__ __forceinline__ void ldsm_x4(uint32_t* r, uint32_t addr) {
    asm volatile("ldmatrix.sync.aligned.m8n8.x4.shared.b16 {%0,%1,%2,%3}, [%4];"
        : "=r"(r[0]), "=r"(r[1]), "=r"(r[2]), "=r"(r[3]) : "r"(addr));
}
// s8 x s8 -> s32, m16n8k32, A row-major, B col-major
__device__ __forceinline__ void imma16832(int32_t* d, const uint32_t* a, const uint32_t* b)
{
    asm volatile(
        "mma.sync.aligned.m16n8k32.row.col.s32.s8.s8.s32 "
        "{%0,%1,%2,%3}, {%4,%5,%6,%7}, {%8,%9}, {%0,%1,%2,%3};"
        : "+r"(d[0]), "+r"(d[1]), "+r"(d[2]), "+r"(d[3])
        : "r"(a[0]), "r"(a[1]), "r"(a[2]), "r"(a[3]),
          "r"(b[0]), "r"(b[1]));
}

// ======================= quantize: fp32 -> s8 sign =======================
__global__ void __launch_bounds__(256)
quant_sign_kernel(const float* __restrict__ in, signed char* __restrict__ out, int n16)
{
    int i = blockIdx.x * 256 + threadIdx.x;
    if (i >= n16) return;
    const float4* p = reinterpret_cast<const float4*>(in) + (size_t)i * 4;
    uint32_t w[4];
#pragma unroll
    for (int j = 0; j < 4; j++) {
        float4 v = p[j];
        uint32_t b0 = v.x > 0.f ? 0x01u : (v.x < 0.f ? 0xFFu : 0x00u);
        uint32_t b1 = v.y > 0.f ? 0x01u : (v.y < 0.f ? 0xFFu : 0x00u);
        uint32_t b2 = v.z > 0.f ? 0x01u : (v.z < 0.f ? 0xFFu : 0x00u);
        uint32_t b3 = v.w > 0.f ? 0x01u : (v.w < 0.f ? 0xFFu : 0x00u);
        w[j] = b0 | (b1 << 8) | (b2 << 16) | (b3 << 24);
    }
    reinterpret_cast<uint4*>(out)[i] = make_uint4(w[0], w[1], w[2], w[3]);
}

// ======================= GEMM kernel =======================
// out[m,n] = sum_k xs[m,k]*ws[n,k] + bias[n]
// 8 warps: warp grid 4(M) x 2(N); warp tile 32 x 64.
// SMEM: 128B rows, swizzle chunk16 ^= (row & 7).
__global__ void __launch_bounds__(256, 2)
tgemm_kernel(const signed char* __restrict__ xs, const signed char* __restrict__ ws,
             const float* __restrict__ bias, float* __restrict__ out)
{
    extern __shared__ unsigned char smem[];
    const uint32_t sb = smem_u32(smem);
    const uint32_t sA = sb + SMEM_A_OFF;
    const uint32_t sB = sb + SMEM_B_OFF;

    const int tid  = threadIdx.x;
    const int wid  = tid >> 5;
    const int lane = tid & 31;

    const int tile_m = blockIdx.y;   // 0..63
    const int tile_n = blockIdx.x;   // 0..15

    const int m_off = (wid >> 1) * 32;   // warp_m 0..3
    const int n_off = (wid & 1) * 64;    // warp_n 0..1

    const signed char* ag0 = xs + (size_t)tile_m * BM * KB;
    const signed char* bg0 = ws + (size_t)tile_n * BN * KB;

    // ---- cp.async stage loader: 1024 16B chunks per matrix, 4 per thread ----
    auto load_stage = [&](int kk, int s) {
        const uint32_t a_s = sA + s * STAGE;
        const uint32_t b_s = sB + s * STAGE;
        const signed char* ag = ag0 + kk * BK;
        const signed char* bg = bg0 + kk * BK;
#pragma unroll
        for (int i = 0; i < 4; i++) {
            int idx = tid + i * 256;
            int r = idx >> 3, c = idx & 7;
            uint32_t d = r * 128 + ((c ^ (r & 7)) << 4);
            cp16(a_s + d, ag + (size_t)r * KB + c * 16);
        }
#pragma unroll
        for (int i = 0; i < 4; i++) {
            int idx = tid + i * 256;
            int r = idx >> 3, c = idx & 7;
            uint32_t d = r * 128 + ((c ^ (r & 7)) << 4);
            cp16(b_s + d, bg + (size_t)r * KB + c * 16);
        }
        cp_commit();
    };

    // ---- ldmatrix lane geometry ----
    // x4: lanes 8i..8i+7 give row addresses of matrix i.
    const int sub = lane >> 3;       // 0..3
    const int l7  = lane & 7;
    // A: mats {m0 k0-15, m8 k0-15, m0 k16-31, m8 k16-31} -> a0..a3
    const int a_row0 = m_off + (sub & 1) * 8 + l7;          // + mt*16
    const int a_csel = sub >> 1;
    // B: mats {n0 klo, n0 khi, n8 klo, n8 khi} -> b0..b3 (two n8-tiles per x4)
    const int b_rowb = n_off + (sub >> 1) * 8 + l7;         // + p*16
    const int b_csel = sub & 1;

    int32_t acc[2][8][4];
#pragma unroll
    for (int mt = 0; mt < 2; mt++)
#pragma unroll
        for (int nt = 0; nt < 8; nt++)
#pragma unroll
            for (int r = 0; r < 4; r++) acc[mt][nt][r] = 0;

    load_stage(0, 0);
    load_stage(1, 1);

    for (int t = 0; t < KITERS; ++t) {
        const int s = t % NS;
        cp_wait<NS - 2>();
        __syncthreads();

        if (t + NS - 1 < KITERS) load_stage(t + NS - 1, (t + NS - 1) % NS);
        else cp_commit();   // keep group numbering aligned

        const uint32_t a_s = sA + s * STAGE;
        const uint32_t b_s = sB + s * STAGE;

#pragma unroll
        for (int ks = 0; ks < 4; ks++) {        // 4 x k32 per BK=128
            uint32_t a[2][4];
#pragma unroll
            for (int mt = 0; mt < 2; mt++) {
                const int r = a_row0 + mt * 16;
                const int c = (2 * ks + a_csel) ^ (r & 7);
                ldsm_x4(a[mt], a_s + r * 128 + (c << 4));
            }
#pragma unroll
            for (int p = 0; p < 4; p++) {       // 2 n8-tiles per iteration
                uint32_t b[4];
                const int r = b_rowb + p * 16;
                const int c = (2 * ks + b_csel) ^ (r & 7);
                ldsm_x4(b, b_s + r * 128 + (c << 4));
                imma16832(acc[0][2 * p],     a[0], b);
                imma16832(acc[0][2 * p + 1], a[0], b + 2);
                imma16832(acc[1][2 * p],     a[1], b);
                imma16832(acc[1][2 * p + 1], a[1], b + 2);
            }
        }
    }

    // ======================= epilogue =======================
    const int qr = lane >> 2;
    const int qc = lane & 3;
    const int gm0 = tile_m * BM + m_off + qr;
    const int gn0 = tile_n * BN + n_off + qc * 2;
#pragma unroll
    for (int mt = 0; mt < 2; mt++) {
#pragma unroll
        for (int nt = 0; nt < 8; nt++) {
            const int col = gn0 + nt * 8;
            const float2 bb = *reinterpret_cast<const float2*>(bias + col);
            const int row0 = gm0 + mt * 16;
            float2 v0, v1;
            v0.x = (float)acc[mt][nt][0] + bb.x;
            v0.y = (float)acc[mt][nt][1] + bb.y;
            v1.x = (float)acc[mt][nt][2] + bb.x;
            v1.y = (float)acc[mt][nt][3] + bb.y;
            *reinterpret_cast<float2*>(out + (size_t)row0 * NB + col) = v0;
            *reinterpret_cast<float2*>(out + (size_t)(row0 + 8) * NB + col) = v1;
        }
    }
}

// ======================= launch =======================
extern "C" void kernel_launch(void* const* d_in, const int* in_sizes, int n_in,
                              void* d_out, int out_size)
{
    const float* x    = (const float*)d_in[0];  // [8192, 2048]
    const float* w    = (const float*)d_in[1];  // [2048, 2048]
    const float* bias = (const float*)d_in[2];  // [2048]
    float* out = (float*)d_out;

    void* xs = nullptr; cudaGetSymbolAddress(&xs, g_xs);
    void* ws = nullptr; cudaGetSymbolAddress(&ws, g_ws);

    const int nx16 = MB * KB / 16;
    const int nw16 = NB * KB / 16;
    quant_sign_kernel<<<(nx16 + 255) / 256, 256>>>(x, (signed char*)xs, nx16);
    quant_sign_kernel<<<(nw16 + 255) / 256, 256>>>(w, (signed char*)ws, nw16);

    cudaFuncSetAttribute(tgemm_kernel, cudaFuncAttributeMaxDynamicSharedMemorySize, SMEM_TOTAL);
    tgemm_kernel<<<dim3(NB / BN, MB / BM), 256, SMEM_TOTAL>>>(
        (const signed char*)xs, (const signed char*)ws, bias, out);
}

// round 5
// speedup vs baseline: 1.1044x; 1.0394x over previous
#include <cuda_runtime.h>
#include <cstdint>

// ======================= problem constants =======================
constexpr int MB = 8192;   // batch (GEMM M)
constexpr int NB = 2048;   // out features (GEMM N)
constexpr int KB = 2048;   // in features (GEMM K)

constexpr int N_IMMA = 1536;             // cols [0,1536) via s8 IMMA
// cols [1536,2048) via bf16 HMMA

constexpr int BM = 128;
constexpr int BN = 128;

// ---- IMMA tiling ----
constexpr int BK8 = 128;                 // 128 s8 = 128B row
constexpr int KIT8 = KB / BK8;           // 16
// ---- HMMA tiling ----
constexpr int BKH = 64;                  // 64 bf16 = 128B row
constexpr int KITH = KB / BKH;           // 32

constexpr int NS = 3;
constexpr int STAGE = BM * 128;          // 16384 B (both kernels: 128 rows x 128B)
constexpr int SMEM_B_OFF = NS * STAGE;
constexpr int SMEM_TOTAL = 2 * NS * STAGE;  // 98304

// scratch
__device__ __align__(16) signed char g_xs[(size_t)MB * KB];        // 16 MB s8
__device__ __align__(16) signed char g_ws[(size_t)NB * KB];        //  4 MB s8
__device__ __align__(16) unsigned short g_xh[(size_t)MB * KB];     // 32 MB bf16
__device__ __align__(16) unsigned short g_wh[(size_t)NB * KB];     //  8 MB bf16

// ======================= helpers =======================
__device__ __forceinline__ uint32_t smem_u32(const void* p) {
    uint32_t a;
    asm("{ .reg .u64 t; cvta.to.shared.u64 t, %1; cvt.u32.u64 %0, t; }" : "=r"(a) : "l"(p));
    return a;
}
__device__ __forceinline__ void cp16(uint32_t dst, const void* src) {
    asm volatile("cp.async.cg.shared.global [%0], [%1], 16;" :: "r"(dst), "l"(src));
}
__device__ __forceinline__ void cp_commit() {
    asm volatile("cp.async.commit_group;" ::: "memory");
}
template <int N>
__device__ __forceinline__ void cp_wait() {
    asm volatile("cp.async.wait_group %0;" :: "n"(N) : "memory");
}
__device__ __forceinline__ void ldsm_x4(uint32_t* r, uint32_t addr) {
    asm volatile("ldmatrix.sync.aligned.m8n8.x4.shared.b16 {%0,%1,%2,%3}, [%4];"
        : "=r"(r[0]), "=r"(r[1]), "=r"(r[2]), "=r"(r[3]) : "r"(addr));
}
__device__ __forceinline__ void imma16832(int32_t* d, const uint32_t* a, const uint32_t* b)
{
    asm volatile(
        "mma.sync.aligned.m16n8k32.row.col.s32.s8.s8.s32 "
        "{%0,%1,%2,%3}, {%4,%5,%6,%7}, {%8,%9}, {%0,%1,%2,%3};"
        : "+r"(d[0]), "+r"(d[1]), "+r"(d[2]), "+r"(d[3])
        : "r"(a[0]), "r"(a[1]), "r"(a[2]), "r"(a[3]),
          "r"(b[0]), "r"(b[1]));
}
__device__ __forceinline__ void hmma16816(float* d, const uint32_t* a, const uint32_t* b)
{
    asm volatile(
        "mma.sync.aligned.m16n8k16.row.col.f32.bf16.bf16.f32 "
        "{%0,%1,%2,%3}, {%4,%5,%6,%7}, {%8,%9}, {%0,%1,%2,%3};"
        : "+f"(d[0]), "+f"(d[1]), "+f"(d[2]), "+f"(d[3])
        : "r"(a[0]), "r"(a[1]), "r"(a[2]), "r"(a[3]),
          "r"(b[0]), "r"(b[1]));
}

// ======================= fused quantize =======================
// s8: +1->0x01 -1->0xFF 0->0x00; bf16: +1->0x3F80 -1->0xBF80 0->0x0000
constexpr int NX16 = MB * KB / 16;       // 1,048,576
constexpr int NW16 = NB * KB / 16;       // 262,144
constexpr int NT16 = NX16 + NW16;

__global__ void __launch_bounds__(256)
quant_fused_kernel(const float* __restrict__ x, const float* __restrict__ w,
                   signed char* __restrict__ xs, signed char* __restrict__ ws,
                   unsigned short* __restrict__ xh, unsigned short* __restrict__ wh)
{
    int i = blockIdx.x * 256 + threadIdx.x;
    if (i >= NT16) return;
    const float4* src;
    uint4* o8;
    uint4* oh;
    if (i < NX16) {
        src = reinterpret_cast<const float4*>(x) + (size_t)i * 4;
        o8 = reinterpret_cast<uint4*>(xs) + i;
        oh = reinterpret_cast<uint4*>(xh) + (size_t)i * 2;
    } else {
        int j = i - NX16;
        src = reinterpret_cast<const float4*>(w) + (size_t)j * 4;
        o8 = reinterpret_cast<uint4*>(ws) + j;
        oh = reinterpret_cast<uint4*>(wh) + (size_t)j * 2;
    }
    uint32_t w8[4];
    uint32_t wh16[8];
#pragma unroll
    for (int j = 0; j < 4; j++) {
        float4 v = src[j];
        uint32_t b0 = v.x > 0.f ? 0x01u : (v.x < 0.f ? 0xFFu : 0x00u);
        uint32_t b1 = v.y > 0.f ? 0x01u : (v.y < 0.f ? 0xFFu : 0x00u);
        uint32_t b2 = v.z > 0.f ? 0x01u : (v.z < 0.f ? 0xFFu : 0x00u);
        uint32_t b3 = v.w > 0.f ? 0x01u : (v.w < 0.f ? 0xFFu : 0x00u);
        w8[j] = b0 | (b1 << 8) | (b2 << 16) | (b3 << 24);
        uint32_t h0 = v.x > 0.f ? 0x3F80u : (v.x < 0.f ? 0xBF80u : 0x0000u);
        uint32_t h1 = v.y > 0.f ? 0x3F80u : (v.y < 0.f ? 0xBF80u : 0x0000u);
        uint32_t h2 = v.z > 0.f ? 0x3F80u : (v.z < 0.f ? 0xBF80u : 0x0000u);
        uint32_t h3 = v.w > 0.f ? 0x3F80u : (v.w < 0.f ? 0xBF80u : 0x0000u);
        wh16[j * 2]     = h0 | (h1 << 16);
        wh16[j * 2 + 1] = h2 | (h3 << 16);
    }
    *o8 = make_uint4(w8[0], w8[1], w8[2], w8[3]);
    oh[0] = make_uint4(wh16[0], wh16[1], wh16[2], wh16[3]);
    oh[1] = make_uint4(wh16[4], wh16[5], wh16[6], wh16[7]);
}

// ======================= IMMA GEMM (cols [0, N_IMMA)) =======================
__global__ void __launch_bounds__(256, 2)
tgemm_imma(const signed char* __restrict__ xs, const signed char* __restrict__ ws,
           const float* __restrict__ bias, float* __restrict__ out)
{
    extern __shared__ unsigned char smem[];
    const uint32_t sb = smem_u32(smem);
    const uint32_t sA = sb;
    const uint32_t sB = sb + SMEM_B_OFF;

    const int tid  = threadIdx.x;
    const int wid  = tid >> 5;
    const int lane = tid & 31;
    const int tile_m = blockIdx.y;
    const int tile_n = blockIdx.x;   // 0..11
    const int m_off = (wid >> 1) * 32;
    const int n_off = (wid & 1) * 64;

    const signed char* ag0 = xs + (size_t)tile_m * BM * KB;
    const signed char* bg0 = ws + (size_t)tile_n * BN * KB;

    auto load_stage = [&](int kk, int s) {
        const uint32_t a_s = sA + s * STAGE;
        const uint32_t b_s = sB + s * STAGE;
        const signed char* ag = ag0 + kk * BK8;
        const signed char* bg = bg0 + kk * BK8;
#pragma unroll
        for (int i = 0; i < 4; i++) {
            int idx = tid + i * 256;
            int r = idx >> 3, c = idx & 7;
            uint32_t d = r * 128 + ((c ^ (r & 7)) << 4);
            cp16(a_s + d, ag + (size_t)r * KB + c * 16);
        }
#pragma unroll
        for (int i = 0; i < 4; i++) {
            int idx = tid + i * 256;
            int r = idx >> 3, c = idx & 7;
            uint32_t d = r * 128 + ((c ^ (r & 7)) << 4);
            cp16(b_s + d, bg + (size_t)r * KB + c * 16);
        }
        cp_commit();
    };

    const int sub = lane >> 3;
    const int l7  = lane & 7;
    const int a_row0 = m_off + (sub & 1) * 8 + l7;
    const int a_csel = sub >> 1;
    const int b_rowb = n_off + (sub >> 1) * 8 + l7;
    const int b_csel = sub & 1;

    int32_t acc[2][8][4];
#pragma unroll
    for (int mt = 0; mt < 2; mt++)
#pragma unroll
        for (int nt = 0; nt < 8; nt++)
#pragma unroll
            for (int r = 0; r < 4; r++) acc[mt][nt][r] = 0;

    load_stage(0, 0);
    load_stage(1, 1);

    for (int t = 0; t < KIT8; ++t) {
        const int s = t % NS;
        cp_wait<NS - 2>();
        __syncthreads();
        if (t + NS - 1 < KIT8) load_stage(t + NS - 1, (t + NS - 1) % NS);
        else cp_commit();

        const uint32_t a_s = sA + s * STAGE;
        const uint32_t b_s = sB + s * STAGE;
#pragma unroll
        for (int ks = 0; ks < 4; ks++) {
            uint32_t a[2][4];
#pragma unroll
            for (int mt = 0; mt < 2; mt++) {
                const int r = a_row0 + mt * 16;
                const int c = (2 * ks + a_csel) ^ (r & 7);
                ldsm_x4(a[mt], a_s + r * 128 + (c << 4));
            }
#pragma unroll
            for (int p = 0; p < 4; p++) {
                uint32_t b[4];
                const int r = b_rowb + p * 16;
                const int c = (2 * ks + b_csel) ^ (r & 7);
                ldsm_x4(b, b_s + r * 128 + (c << 4));
                imma16832(acc[0][2 * p],     a[0], b);
                imma16832(acc[0][2 * p + 1], a[0], b + 2);
                imma16832(acc[1][2 * p],     a[1], b);
                imma16832(acc[1][2 * p + 1], a[1], b + 2);
            }
        }
    }

    const int qr = lane >> 2;
    const int qc = lane & 3;
    const int gm0 = tile_m * BM + m_off + qr;
    const int gn0 = tile_n * BN + n_off + qc * 2;
#pragma unroll
    for (int mt = 0; mt < 2; mt++) {
#pragma unroll
        for (int nt = 0; nt < 8; nt++) {
            const int col = gn0 + nt * 8;
            const float2 bb = *reinterpret_cast<const float2*>(bias + col);
            const int row0 = gm0 + mt * 16;
            float2 v0, v1;
            v0.x = (float)acc[mt][nt][0] + bb.x;
            v0.y = (float)acc[mt][nt][1] + bb.y;
            v1.x = (float)acc[mt][nt][2] + bb.x;
            v1.y = (float)acc[mt][nt][3] + bb.y;
            *reinterpret_cast<float2*>(out + (size_t)row0 * NB + col) = v0;
            *reinterpret_cast<float2*>(out + (size_t)(row0 + 8) * NB + col) = v1;
        }
    }
}

// ======================= HMMA GEMM (cols [N_IMMA, NB)) =======================
__global__ void __launch_bounds__(256, 2)
tgemm_hmma(const unsigned short* __restrict__ xh, const unsigned short* __restrict__ wh,
           const float* __restrict__ bias, float* __restrict__ out)
{
    extern __shared__ unsigned char smem[];
    const uint32_t sb = smem_u32(smem);
    const uint32_t sA = sb;
    const uint32_t sB = sb + SMEM_B_OFF;

    const int tid  = threadIdx.x;
    const int wid  = tid >> 5;
    const int lane = tid & 31;
    const int tile_m = blockIdx.y;
    const int tile_n = blockIdx.x;   // 0..3
    const int m_off = (wid >> 1) * 32;
    const int n_off = (wid & 1) * 64;

    const unsigned char* ag0 = reinterpret_cast<const unsigned char*>(xh + (size_t)tile_m * BM * KB);
    const unsigned char* bg0 = reinterpret_cast<const unsigned char*>(wh + (size_t)(N_IMMA + tile_n * BN) * KB);

    // per-stage: 128 rows x 128B (= 64 bf16) per matrix
    auto load_stage = [&](int kk, int s) {
        const uint32_t a_s = sA + s * STAGE;
        const uint32_t b_s = sB + s * STAGE;
        const unsigned char* ag = ag0 + kk * BKH * 2;   // byte offset in a row
        const unsigned char* bg = bg0 + kk * BKH * 2;
#pragma unroll
        for (int i = 0; i < 4; i++) {
            int idx = tid + i * 256;
            int r = idx >> 3, c = idx & 7;
            uint32_t d = r * 128 + ((c ^ (r & 7)) << 4);
            cp16(a_s + d, ag + (size_t)r * KB * 2 + c * 16);
        }
#pragma unroll
        for (int i = 0; i < 4; i++) {
            int idx = tid + i * 256;
            int r = idx >> 3, c = idx & 7;
            uint32_t d = r * 128 + ((c ^ (r & 7)) << 4);
            cp16(b_s + d, bg + (size_t)r * KB * 2 + c * 16);
        }
        cp_commit();
    };

    const int sub = lane >> 3;
    const int l7  = lane & 7;
    const int a_row0 = m_off + (sub & 1) * 8 + l7;
    const int a_csel = sub >> 1;
    const int b_rowb = n_off + (sub >> 1) * 8 + l7;
    const int b_csel = sub & 1;

    float acc[2][8][4];
#pragma unroll
    for (int mt = 0; mt < 2; mt++)
#pragma unroll
        for (int nt = 0; nt < 8; nt++)
#pragma unroll
            for (int r = 0; r < 4; r++) acc[mt][nt][r] = 0.f;

    load_stage(0, 0);
    load_stage(1, 1);

    for (int t = 0; t < KITH; ++t) {
        const int s = t % NS;
        cp_wait<NS - 2>();
        __syncthreads();
        if (t + NS - 1 < KITH) load_stage(t + NS - 1, (t + NS - 1) % NS);
        else cp_commit();

        const uint32_t a_s = sA + s * STAGE;
        const uint32_t b_s = sB + s * STAGE;
#pragma unroll
        for (int ks = 0; ks < 4; ks++) {        // 4 x k16 per BKH=64
            uint32_t a[2][4];
#pragma unroll
            for (int mt = 0; mt < 2; mt++) {
                const int r = a_row0 + mt * 16;
                const int c = (2 * ks + a_csel) ^ (r & 7);
                ldsm_x4(a[mt], a_s + r * 128 + (c << 4));
            }
#pragma unroll
            for (int p = 0; p < 4; p++) {
                uint32_t b[4];
                const int r = b_rowb + p * 16;
                const int c = (2 * ks + b_csel) ^ (r & 7);
                ldsm_x4(b, b_s + r * 128 + (c << 4));
                hmma16816(acc[0][2 * p],     a[0], b);
                hmma16816(acc[0][2 * p + 1], a[0], b + 2);
                hmma16816(acc[1][2 * p],     a[1], b);
                hmma16816(acc[1][2 * p + 1], a[1], b + 2);
            }
        }
    }

    const int qr = lane >> 2;
    const int qc = lane & 3;
    const int gm0 = tile_m * BM + m_off + qr;
    const int gn0 = N_IMMA + tile_n * BN + n_off + qc * 2;
#pragma unroll
    for (int mt = 0; mt < 2; mt++) {
#pragma unroll
        for (int nt = 0; nt < 8; nt++) {
            const int col = gn0 + nt * 8;
            const float2 bb = *reinterpret_cast<const float2*>(bias + col);
            const int row0 = gm0 + mt * 16;
            float2 v0, v1;
            v0.x = acc[mt][nt][0] + bb.x;
            v0.y = acc[mt][nt][1] + bb.y;
            v1.x = acc[mt][nt][2] + bb.x;
            v1.y = acc[mt][nt][3] + bb.y;
            *reinterpret_cast<float2*>(out + (size_t)row0 * NB + col) = v0;
            *reinterpret_cast<float2*>(out + (size_t)(row0 + 8) * NB + col) = v1;
        }
    }
}

// ======================= launch =======================
extern "C" void kernel_launch(void* const* d_in, const int* in_sizes, int n_in,
                              void* d_out, int out_size)
{
    const float* x    = (const float*)d_in[0];
    const float* w    = (const float*)d_in[1];
    const float* bias = (const float*)d_in[2];
    float* out = (float*)d_out;

    void* xs; cudaGetSymbolAddress(&xs, g_xs);
    void* ws; cudaGetSymbolAddress(&ws, g_ws);
    void* xh; cudaGetSymbolAddress(&xh, g_xh);
    void* wh; cudaGetSymbolAddress(&wh, g_wh);

    quant_fused_kernel<<<(NT16 + 255) / 256, 256>>>(
        x, w, (signed char*)xs, (signed char*)ws,
        (unsigned short*)xh, (unsigned short*)wh);

    cudaFuncSetAttribute(tgemm_imma, cudaFuncAttributeMaxDynamicSharedMemorySize, SMEM_TOTAL);
    cudaFuncSetAttribute(tgemm_hmma, cudaFuncAttributeMaxDynamicSharedMemorySize, SMEM_TOTAL);

    tgemm_imma<<<dim3(N_IMMA / BN, MB / BM), 256, SMEM_TOTAL>>>(
        (const signed char*)xs, (const signed char*)ws, bias, out);
    tgemm_hmma<<<dim3((NB - N_IMMA) / BN, MB / BM), 256, SMEM_TOTAL>>>(
        (const unsigned short*)xh, (const unsigned short*)wh, bias, out);
}

// round 6
// speedup vs baseline: 1.3002x; 1.1773x over previous
#include <cuda_runtime.h>
#include <cstdint>

// ======================= problem constants =======================
constexpr int MB = 8192;   // batch (GEMM M)
constexpr int NB = 2048;   // out features (GEMM N)
constexpr int KB = 2048;   // in features (GEMM K)

constexpr int N_IMMA = 1024;   // cols [0,1024) via s8 IMMA; [1024,2048) via e4m3 FP8

constexpr int BM = 128;
constexpr int BN = 128;
constexpr int BK = 128;            // 128 bytes = one smem row (s8 or e4m3)
constexpr int KITERS = KB / BK;    // 16
constexpr int NS = 3;

constexpr int STAGE = BM * BK;     // 16384
constexpr int SMEM_B_OFF = NS * STAGE;
constexpr int SMEM_TOTAL = 2 * NS * STAGE;  // 98304

// scratch: s8 signs + e4m3 signs
__device__ __align__(16) signed char   g_xs[(size_t)MB * KB];  // 16 MB
__device__ __align__(16) signed char   g_ws[(size_t)NB * KB];  //  4 MB
__device__ __align__(16) unsigned char g_xf[(size_t)MB * KB];  // 16 MB
__device__ __align__(16) unsigned char g_wf[(size_t)NB * KB];  //  4 MB

// ======================= helpers =======================
__device__ __forceinline__ uint32_t smem_u32(const void* p) {
    uint32_t a;
    asm("{ .reg .u64 t; cvta.to.shared.u64 t, %1; cvt.u32.u64 %0, t; }" : "=r"(a) : "l"(p));
    return a;
}
__device__ __forceinline__ void cp16(uint32_t dst, const void* src) {
    asm volatile("cp.async.cg.shared.global [%0], [%1], 16;" :: "r"(dst), "l"(src));
}
__device__ __forceinline__ void cp_commit() {
    asm volatile("cp.async.commit_group;" ::: "memory");
}
template <int N>
__device__ __forceinline__ void cp_wait() {
    asm volatile("cp.async.wait_group %0;" :: "n"(N) : "memory");
}
__device__ __forceinline__ void ldsm_x4(uint32_t* r, uint32_t addr) {
    asm volatile("ldmatrix.sync.aligned.m8n8.x4.shared.b16 {%0,%1,%2,%3}, [%4];"
        : "=r"(r[0]), "=r"(r[1]), "=r"(r[2]), "=r"(r[3]) : "r"(addr));
}
__device__ __forceinline__ void imma16832(int32_t* d, const uint32_t* a, const uint32_t* b)
{
    asm volatile(
        "mma.sync.aligned.m16n8k32.row.col.s32.s8.s8.s32 "
        "{%0,%1,%2,%3}, {%4,%5,%6,%7}, {%8,%9}, {%0,%1,%2,%3};"
        : "+r"(d[0]), "+r"(d[1]), "+r"(d[2]), "+r"(d[3])
        : "r"(a[0]), "r"(a[1]), "r"(a[2]), "r"(a[3]),
          "r"(b[0]), "r"(b[1]));
}
__device__ __forceinline__ void fmma16832(float* d, const uint32_t* a, const uint32_t* b)
{
    asm volatile(
        "mma.sync.aligned.m16n8k32.row.col.f32.e4m3.e4m3.f32 "
        "{%0,%1,%2,%3}, {%4,%5,%6,%7}, {%8,%9}, {%0,%1,%2,%3};"
        : "+f"(d[0]), "+f"(d[1]), "+f"(d[2]), "+f"(d[3])
        : "r"(a[0]), "r"(a[1]), "r"(a[2]), "r"(a[3]),
          "r"(b[0]), "r"(b[1]));
}

// ======================= fused quantize =======================
// s8: +1->0x01 -1->0xFF 0->0x00 ; e4m3: +1->0x38 -1->0xB8 0->0x00
constexpr int NX16 = MB * KB / 16;
constexpr int NW16 = NB * KB / 16;
constexpr int NT16 = NX16 + NW16;

__global__ void __launch_bounds__(256)
quant_fused_kernel(const float* __restrict__ x, const float* __restrict__ w,
                   signed char* __restrict__ xs, signed char* __restrict__ ws,
                   unsigned char* __restrict__ xf, unsigned char* __restrict__ wf)
{
    int i = blockIdx.x * 256 + threadIdx.x;
    if (i >= NT16) return;
    const float4* src;
    uint4* o8;
    uint4* of;
    if (i < NX16) {
        src = reinterpret_cast<const float4*>(x) + (size_t)i * 4;
        o8 = reinterpret_cast<uint4*>(xs) + i;
        of = reinterpret_cast<uint4*>(xf) + i;
    } else {
        int j = i - NX16;
        src = reinterpret_cast<const float4*>(w) + (size_t)j * 4;
        o8 = reinterpret_cast<uint4*>(ws) + j;
        of = reinterpret_cast<uint4*>(wf) + j;
    }
    uint32_t w8[4], w38[4];
#pragma unroll
    for (int j = 0; j < 4; j++) {
        float4 v = src[j];
        uint32_t b0 = v.x > 0.f ? 0x01u : (v.x < 0.f ? 0xFFu : 0x00u);
        uint32_t b1 = v.y > 0.f ? 0x01u : (v.y < 0.f ? 0xFFu : 0x00u);
        uint32_t b2 = v.z > 0.f ? 0x01u : (v.z < 0.f ? 0xFFu : 0x00u);
        uint32_t b3 = v.w > 0.f ? 0x01u : (v.w < 0.f ? 0xFFu : 0x00u);
        w8[j] = b0 | (b1 << 8) | (b2 << 16) | (b3 << 24);
        uint32_t f0 = v.x > 0.f ? 0x38u : (v.x < 0.f ? 0xB8u : 0x00u);
        uint32_t f1 = v.y > 0.f ? 0x38u : (v.y < 0.f ? 0xB8u : 0x00u);
        uint32_t f2 = v.z > 0.f ? 0x38u : (v.z < 0.f ? 0xB8u : 0x00u);
        uint32_t f3 = v.w > 0.f ? 0x38u : (v.w < 0.f ? 0xB8u : 0x00u);
        w38[j] = f0 | (f1 << 8) | (f2 << 16) | (f3 << 24);
    }
    *o8 = make_uint4(w8[0], w8[1], w8[2], w8[3]);
    *of = make_uint4(w38[0], w38[1], w38[2], w38[3]);
}

// ======================= IMMA GEMM (cols [0, N_IMMA)) =======================
__global__ void __launch_bounds__(256, 2)
tgemm_imma(const signed char* __restrict__ xs, const signed char* __restrict__ ws,
           const float* __restrict__ bias, float* __restrict__ out)
{
    extern __shared__ unsigned char smem[];
    const uint32_t sb = smem_u32(smem);
    const uint32_t sA = sb;
    const uint32_t sB = sb + SMEM_B_OFF;

    const int tid  = threadIdx.x;
    const int wid  = tid >> 5;
    const int lane = tid & 31;
    const int tile_m = blockIdx.y;
    const int tile_n = blockIdx.x;
    const int m_off = (wid >> 1) * 32;
    const int n_off = (wid & 1) * 64;

    const signed char* ag0 = xs + (size_t)tile_m * BM * KB;
    const signed char* bg0 = ws + (size_t)tile_n * BN * KB;

    auto load_stage = [&](int kk, int s) {
        const uint32_t a_s = sA + s * STAGE;
        const uint32_t b_s = sB + s * STAGE;
        const signed char* ag = ag0 + kk * BK;
        const signed char* bg = bg0 + kk * BK;
#pragma unroll
        for (int i = 0; i < 4; i++) {
            int idx = tid + i * 256;
            int r = idx >> 3, c = idx & 7;
            uint32_t d = r * 128 + ((c ^ (r & 7)) << 4);
            cp16(a_s + d, ag + (size_t)r * KB + c * 16);
        }
#pragma unroll
        for (int i = 0; i < 4; i++) {
            int idx = tid + i * 256;
            int r = idx >> 3, c = idx & 7;
            uint32_t d = r * 128 + ((c ^ (r & 7)) << 4);
            cp16(b_s + d, bg + (size_t)r * KB + c * 16);
        }
        cp_commit();
    };

    const int sub = lane >> 3;
    const int l7  = lane & 7;
    const int a_row0 = m_off + (sub & 1) * 8 + l7;
    const int a_csel = sub >> 1;
    const int b_rowb = n_off + (sub >> 1) * 8 + l7;
    const int b_csel = sub & 1;

    int32_t acc[2][8][4];
#pragma unroll
    for (int mt = 0; mt < 2; mt++)
#pragma unroll
        for (int nt = 0; nt < 8; nt++)
#pragma unroll
            for (int r = 0; r < 4; r++) acc[mt][nt][r] = 0;

    load_stage(0, 0);
    load_stage(1, 1);

    for (int t = 0; t < KITERS; ++t) {
        const int s = t % NS;
        cp_wait<NS - 2>();
        __syncthreads();
        if (t + NS - 1 < KITERS) load_stage(t + NS - 1, (t + NS - 1) % NS);
        else cp_commit();

        const uint32_t a_s = sA + s * STAGE;
        const uint32_t b_s = sB + s * STAGE;
#pragma unroll
        for (int ks = 0; ks < 4; ks++) {
            uint32_t a[2][4];
#pragma unroll
            for (int mt = 0; mt < 2; mt++) {
                const int r = a_row0 + mt * 16;
                const int c = (2 * ks + a_csel) ^ (r & 7);
                ldsm_x4(a[mt], a_s + r * 128 + (c << 4));
            }
#pragma unroll
            for (int p = 0; p < 4; p++) {
                uint32_t b[4];
                const int r = b_rowb + p * 16;
                const int c = (2 * ks + b_csel) ^ (r & 7);
                ldsm_x4(b, b_s + r * 128 + (c << 4));
                imma16832(acc[0][2 * p],     a[0], b);
                imma16832(acc[0][2 * p + 1], a[0], b + 2);
                imma16832(acc[1][2 * p],     a[1], b);
                imma16832(acc[1][2 * p + 1], a[1], b + 2);
            }
        }
    }

    const int qr = lane >> 2;
    const int qc = lane & 3;
    const int gm0 = tile_m * BM + m_off + qr;
    const int gn0 = tile_n * BN + n_off + qc * 2;
#pragma unroll
    for (int mt = 0; mt < 2; mt++) {
#pragma unroll
        for (int nt = 0; nt < 8; nt++) {
            const int col = gn0 + nt * 8;
            const float2 bb = *reinterpret_cast<const float2*>(bias + col);
            const int row0 = gm0 + mt * 16;
            float2 v0, v1;
            v0.x = (float)acc[mt][nt][0] + bb.x;
            v0.y = (float)acc[mt][nt][1] + bb.y;
            v1.x = (float)acc[mt][nt][2] + bb.x;
            v1.y = (float)acc[mt][nt][3] + bb.y;
            *reinterpret_cast<float2*>(out + (size_t)row0 * NB + col) = v0;
            *reinterpret_cast<float2*>(out + (size_t)(row0 + 8) * NB + col) = v1;
        }
    }
}

// ======================= FP8 GEMM (cols [N_IMMA, NB)) =======================
__global__ void __launch_bounds__(256, 2)
tgemm_fp8(const unsigned char* __restrict__ xf, const unsigned char* __restrict__ wf,
          const float* __restrict__ bias, float* __restrict__ out)
{
    extern __shared__ unsigned char smem[];
    const uint32_t sb = smem_u32(smem);
    const uint32_t sA = sb;
    const uint32_t sB = sb + SMEM_B_OFF;

    const int tid  = threadIdx.x;
    const int wid  = tid >> 5;
    const int lane = tid & 31;
    const int tile_m = blockIdx.y;
    const int tile_n = blockIdx.x;
    const int m_off = (wid >> 1) * 32;
    const int n_off = (wid & 1) * 64;

    const unsigned char* ag0 = xf + (size_t)tile_m * BM * KB;
    const unsigned char* bg0 = wf + (size_t)(N_IMMA + tile_n * BN) * KB;

    auto load_stage = [&](int kk, int s) {
        const uint32_t a_s = sA + s * STAGE;
        const uint32_t b_s = sB + s * STAGE;
        const unsigned char* ag = ag0 + kk * BK;
        const unsigned char* bg = bg0 + kk * BK;
#pragma unroll
        for (int i = 0; i < 4; i++) {
            int idx = tid + i * 256;
            int r = idx >> 3, c = idx & 7;
            uint32_t d = r * 128 + ((c ^ (r & 7)) << 4);
            cp16(a_s + d, ag + (size_t)r * KB + c * 16);
        }
#pragma unroll
        for (int i = 0; i < 4; i++) {
            int idx = tid + i * 256;
            int r = idx >> 3, c = idx & 7;
            uint32_t d = r * 128 + ((c ^ (r & 7)) << 4);
            cp16(b_s + d, bg + (size_t)r * KB + c * 16);
        }
        cp_commit();
    };

    const int sub = lane >> 3;
    const int l7  = lane & 7;
    const int a_row0 = m_off + (sub & 1) * 8 + l7;
    const int a_csel = sub >> 1;
    const int b_rowb = n_off + (sub >> 1) * 8 + l7;
    const int b_csel = sub & 1;

    float acc[2][8][4];
#pragma unroll
    for (int mt = 0; mt < 2; mt++)
#pragma unroll
        for (int nt = 0; nt < 8; nt++)
#pragma unroll
            for (int r = 0; r < 4; r++) acc[mt][nt][r] = 0.f;

    load_stage(0, 0);
    load_stage(1, 1);

    for (int t = 0; t < KITERS; ++t) {
        const int s = t % NS;
        cp_wait<NS - 2>();
        __syncthreads();
        if (t + NS - 1 < KITERS) load_stage(t + NS - 1, (t + NS - 1) % NS);
        else cp_commit();

        const uint32_t a_s = sA + s * STAGE;
        const uint32_t b_s = sB + s * STAGE;
#pragma unroll
        for (int ks = 0; ks < 4; ks++) {
            uint32_t a[2][4];
#pragma unroll
            for (int mt = 0; mt < 2; mt++) {
                const int r = a_row0 + mt * 16;
                const int c = (2 * ks + a_csel) ^ (r & 7);
                ldsm_x4(a[mt], a_s + r * 128 + (c << 4));
            }
#pragma unroll
            for (int p = 0; p < 4; p++) {
                uint32_t b[4];
                const int r = b_rowb + p * 16;
                const int c = (2 * ks + b_csel) ^ (r & 7);
                ldsm_x4(b, b_s + r * 128 + (c << 4));
                fmma16832(acc[0][2 * p],     a[0], b);
                fmma16832(acc[0][2 * p + 1], a[0], b + 2);
                fmma16832(acc[1][2 * p],     a[1], b);
                fmma16832(acc[1][2 * p + 1], a[1], b + 2);
            }
        }
    }

    const int qr = lane >> 2;
    const int qc = lane & 3;
    const int gm0 = tile_m * BM + m_off + qr;
    const int gn0 = N_IMMA + tile_n * BN + n_off + qc * 2;
#pragma unroll
    for (int mt = 0; mt < 2; mt++) {
#pragma unroll
        for (int nt = 0; nt < 8; nt++) {
            const int col = gn0 + nt * 8;
            const float2 bb = *reinterpret_cast<const float2*>(bias + col);
            const int row0 = gm0 + mt * 16;
            float2 v0, v1;
            v0.x = acc[mt][nt][0] + bb.x;
            v0.y = acc[mt][nt][1] + bb.y;
            v1.x = acc[mt][nt][2] + bb.x;
            v1.y = acc[mt][nt][3] + bb.y;
            *reinterpret_cast<float2*>(out + (size_t)row0 * NB + col) = v0;
            *reinterpret_cast<float2*>(out + (size_t)(row0 + 8) * NB + col) = v1;
        }
    }
}

// ======================= launch =======================
extern "C" void kernel_launch(void* const* d_in, const int* in_sizes, int n_in,
                              void* d_out, int out_size)
{
    const float* x    = (const float*)d_in[0];
    const float* w    = (const float*)d_in[1];
    const float* bias = (const float*)d_in[2];
    float* out = (float*)d_out;

    void* xs; cudaGetSymbolAddress(&xs, g_xs);
    void* ws; cudaGetSymbolAddress(&ws, g_ws);
    void* xf; cudaGetSymbolAddress(&xf, g_xf);
    void* wf; cudaGetSymbolAddress(&wf, g_wf);

    quant_fused_kernel<<<(NT16 + 255) / 256, 256>>>(
        x, w, (signed char*)xs, (signed char*)ws,
        (unsigned char*)xf, (unsigned char*)wf);

    cudaFuncSetAttribute(tgemm_imma, cudaFuncAttributeMaxDynamicSharedMemorySize, SMEM_TOTAL);
    cudaFuncSetAttribute(tgemm_fp8, cudaFuncAttributeMaxDynamicSharedMemorySize, SMEM_TOTAL);

    tgemm_fp8<<<dim3((NB - N_IMMA) / BN, MB / BM), 256, SMEM_TOTAL>>>(
        (const unsigned char*)xf, (const unsigned char*)wf, bias, out);
    tgemm_imma<<<dim3(N_IMMA / BN, MB / BM), 256, SMEM_TOTAL>>>(
        (const signed char*)xs, (const signed char*)ws, bias, out);
}

// round 7
// speedup vs baseline: 2.5365x; 1.9508x over previous
#include <cuda_runtime.h>
#include <cstdint>

// ======================= problem constants =======================
constexpr int MB = 8192;   // batch (GEMM M)
constexpr int NB = 2048;   // out features (GEMM N)
constexpr int KB = 2048;   // in features (GEMM K)

constexpr int BM = 128;
constexpr int BN = 128;
constexpr int BK = 128;            // 128 e4m3 bytes = one smem row
constexpr int KITERS = KB / BK;    // 16
constexpr int NS = 3;

constexpr int STAGE = BM * BK;     // 16384
constexpr int SMEM_B_OFF = NS * STAGE;
constexpr int SMEM_TOTAL = 2 * NS * STAGE;  // 98304

// e4m3 sign scratch
__device__ __align__(16) unsigned char g_xf[(size_t)MB * KB];  // 16 MB
__device__ __align__(16) unsigned char g_wf[(size_t)NB * KB];  //  4 MB

// ======================= helpers =======================
__device__ __forceinline__ uint32_t smem_u32(const void* p) {
    uint32_t a;
    asm("{ .reg .u64 t; cvta.to.shared.u64 t, %1; cvt.u32.u64 %0, t; }" : "=r"(a) : "l"(p));
    return a;
}
__device__ __forceinline__ void cp16(uint32_t dst, const void* src) {
    asm volatile("cp.async.cg.shared.global [%0], [%1], 16;" :: "r"(dst), "l"(src));
}
__device__ __forceinline__ void cp_commit() {
    asm volatile("cp.async.commit_group;" ::: "memory");
}
template <int N>
__device__ __forceinline__ void cp_wait() {
    asm volatile("cp.async.wait_group %0;" :: "n"(N) : "memory");
}
__device__ __forceinline__ void ldsm_x4(uint32_t* r, uint32_t addr) {
    asm volatile("ldmatrix.sync.aligned.m8n8.x4.shared.b16 {%0,%1,%2,%3}, [%4];"
        : "=r"(r[0]), "=r"(r[1]), "=r"(r[2]), "=r"(r[3]) : "r"(addr));
}
__device__ __forceinline__ void fmma16832(float* d, const uint32_t* a, const uint32_t* b)
{
    asm volatile(
        "mma.sync.aligned.m16n8k32.row.col.f32.e4m3.e4m3.f32 "
        "{%0,%1,%2,%3}, {%4,%5,%6,%7}, {%8,%9}, {%0,%1,%2,%3};"
        : "+f"(d[0]), "+f"(d[1]), "+f"(d[2]), "+f"(d[3])
        : "r"(a[0]), "r"(a[1]), "r"(a[2]), "r"(a[3]),
          "r"(b[0]), "r"(b[1]));
}

// ======================= quantize: fp32 -> e4m3 sign =======================
// +1 -> 0x38, -1 -> 0xB8, 0 -> 0x00
constexpr int NX16 = MB * KB / 16;
constexpr int NW16 = NB * KB / 16;
constexpr int NT16 = NX16 + NW16;

__global__ void __launch_bounds__(256)
quant_fp8_kernel(const float* __restrict__ x, const float* __restrict__ w,
                 unsigned char* __restrict__ xf, unsigned char* __restrict__ wf)
{
    int i = blockIdx.x * 256 + threadIdx.x;
    if (i >= NT16) return;
    const float4* src;
    uint4* of;
    if (i < NX16) {
        src = reinterpret_cast<const float4*>(x) + (size_t)i * 4;
        of = reinterpret_cast<uint4*>(xf) + i;
    } else {
        int j = i - NX16;
        src = reinterpret_cast<const float4*>(w) + (size_t)j * 4;
        of = reinterpret_cast<uint4*>(wf) + j;
    }
    uint32_t w38[4];
#pragma unroll
    for (int j = 0; j < 4; j++) {
        float4 v = src[j];
        uint32_t f0 = v.x > 0.f ? 0x38u : (v.x < 0.f ? 0xB8u : 0x00u);
        uint32_t f1 = v.y > 0.f ? 0x38u : (v.y < 0.f ? 0xB8u : 0x00u);
        uint32_t f2 = v.z > 0.f ? 0x38u : (v.z < 0.f ? 0xB8u : 0x00u);
        uint32_t f3 = v.w > 0.f ? 0x38u : (v.w < 0.f ? 0xB8u : 0x00u);
        w38[j] = f0 | (f1 << 8) | (f2 << 16) | (f3 << 24);
    }
    *of = make_uint4(w38[0], w38[1], w38[2], w38[3]);
}

// ======================= FP8 GEMM (full N) =======================
// out[m,n] = sum_k xf[m,k]*wf[n,k] + bias[n]
// 8 warps: warp grid 4(M) x 2(N); warp tile 32 x 64.
__global__ void __launch_bounds__(256, 2)
tgemm_fp8(const unsigned char* __restrict__ xf, const unsigned char* __restrict__ wf,
          const float* __restrict__ bias, float* __restrict__ out)
{
    extern __shared__ unsigned char smem[];
    const uint32_t sb = smem_u32(smem);
    const uint32_t sA = sb;
    const uint32_t sB = sb + SMEM_B_OFF;

    const int tid  = threadIdx.x;
    const int wid  = tid >> 5;
    const int lane = tid & 31;
    const int tile_m = blockIdx.y;
    const int tile_n = blockIdx.x;   // 0..15
    const int m_off = (wid >> 1) * 32;
    const int n_off = (wid & 1) * 64;

    const unsigned char* ag0 = xf + (size_t)tile_m * BM * KB;
    const unsigned char* bg0 = wf + (size_t)tile_n * BN * KB;

    auto load_stage = [&](int kk, int s) {
        const uint32_t a_s = sA + s * STAGE;
        const uint32_t b_s = sB + s * STAGE;
        const unsigned char* ag = ag0 + kk * BK;
        const unsigned char* bg = bg0 + kk * BK;
#pragma unroll
        for (int i = 0; i < 4; i++) {
            int idx = tid + i * 256;
            int r = idx >> 3, c = idx & 7;
            uint32_t d = r * 128 + ((c ^ (r & 7)) << 4);
            cp16(a_s + d, ag + (size_t)r * KB + c * 16);
        }
#pragma unroll
        for (int i = 0; i < 4; i++) {
            int idx = tid + i * 256;
            int r = idx >> 3, c = idx & 7;
            uint32_t d = r * 128 + ((c ^ (r & 7)) << 4);
            cp16(b_s + d, bg + (size_t)r * KB + c * 16);
        }
        cp_commit();
    };

    const int sub = lane >> 3;
    const int l7  = lane & 7;
    const int a_row0 = m_off + (sub & 1) * 8 + l7;
    const int a_csel = sub >> 1;
    const int b_rowb = n_off + (sub >> 1) * 8 + l7;
    const int b_csel = sub & 1;

    float acc[2][8][4];
#pragma unroll
    for (int mt = 0; mt < 2; mt++)
#pragma unroll
        for (int nt = 0; nt < 8; nt++)
#pragma unroll
            for (int r = 0; r < 4; r++) acc[mt][nt][r] = 0.f;

    load_stage(0, 0);
    load_stage(1, 1);

    for (int t = 0; t < KITERS; ++t) {
        const int s = t % NS;
        cp_wait<NS - 2>();
        __syncthreads();
        if (t + NS - 1 < KITERS) load_stage(t + NS - 1, (t + NS - 1) % NS);
        else cp_commit();

        const uint32_t a_s = sA + s * STAGE;
        const uint32_t b_s = sB + s * STAGE;
#pragma unroll
        for (int ks = 0; ks < 4; ks++) {
            uint32_t a[2][4];
#pragma unroll
            for (int mt = 0; mt < 2; mt++) {
                const int r = a_row0 + mt * 16;
                const int c = (2 * ks + a_csel) ^ (r & 7);
                ldsm_x4(a[mt], a_s + r * 128 + (c << 4));
            }
#pragma unroll
            for (int p = 0; p < 4; p++) {
                uint32_t b[4];
                const int r = b_rowb + p * 16;
                const int c = (2 * ks + b_csel) ^ (r & 7);
                ldsm_x4(b, b_s + r * 128 + (c << 4));
                fmma16832(acc[0][2 * p],     a[0], b);
                fmma16832(acc[0][2 * p + 1], a[0], b + 2);
                fmma16832(acc[1][2 * p],     a[1], b);
                fmma16832(acc[1][2 * p + 1], a[1], b + 2);
            }
        }
    }

    const int qr = lane >> 2;
    const int qc = lane & 3;
    const int gm0 = tile_m * BM + m_off + qr;
    const int gn0 = tile_n * BN + n_off + qc * 2;
#pragma unroll
    for (int mt = 0; mt < 2; mt++) {
#pragma unroll
        for (int nt = 0; nt < 8; nt++) {
            const int col = gn0 + nt * 8;
            const float2 bb = *reinterpret_cast<const float2*>(bias + col);
            const int row0 = gm0 + mt * 16;
            float2 v0, v1;
            v0.x = acc[mt][nt][0] + bb.x;
            v0.y = acc[mt][nt][1] + bb.y;
            v1.x = acc[mt][nt][2] + bb.x;
            v1.y = acc[mt][nt][3] + bb.y;
            *reinterpret_cast<float2*>(out + (size_t)row0 * NB + col) = v0;
            *reinterpret_cast<float2*>(out + (size_t)(row0 + 8) * NB + col) = v1;
        }
    }
}

// ======================= launch =======================
extern "C" void kernel_launch(void* const* d_in, const int* in_sizes, int n_in,
                              void* d_out, int out_size)
{
    const float* x    = (const float*)d_in[0];
    const float* w    = (const float*)d_in[1];
    const float* bias = (const float*)d_in[2];
    float* out = (float*)d_out;

    void* xf; cudaGetSymbolAddress(&xf, g_xf);
    void* wf; cudaGetSymbolAddress(&wf, g_wf);

    quant_fp8_kernel<<<(NT16 + 255) / 256, 256>>>(
        x, w, (unsigned char*)xf, (unsigned char*)wf);

    cudaFuncSetAttribute(tgemm_fp8, cudaFuncAttributeMaxDynamicSharedMemorySize, SMEM_TOTAL);
    tgemm_fp8<<<dim3(NB / BN, MB / BM), 256, SMEM_TOTAL>>>(
        (const unsigned char*)xf, (const unsigned char*)wf, bias, out);
}